// round 15
// baseline (speedup 1.0000x reference)
#include <cuda_runtime.h>
#include <cuda_bf16.h>
#include <cstdint>

#define CH 32
#define KNB 27
#define TM 128
#define NPAD 2000128
#define SM_IDX 49152
#define SM_TOT 53248

__device__ __align__(128) uint32_t g_xp [(size_t)NPAD * 32];
__device__ __align__(128) uint32_t g_h1p[(size_t)NPAD * 32];
__device__ __align__(128) float    g_h1 [(size_t)NPAD * 32];
__device__ __align__(128) int      g_nbrT[(size_t)KNB * NPAD];
__device__ __align__(128) uint32_t g_w1img[KNB * 1024];
__device__ __align__(128) uint32_t g_w2img[KNB * 1024];
__device__ float g_part[15700 * 64];
__device__ float g_bn[64];

__device__ __forceinline__ void cpa16s(uint32_t d, const void* s) {
    asm volatile("cp.async.cg.shared.global [%0], [%1], 16;" :: "r"(d), "l"(s));
}
__device__ __forceinline__ void ldm4(uint32_t* r, uint32_t a) {
    asm volatile("ldmatrix.sync.aligned.m8n8.x4.shared.b16 {%0,%1,%2,%3}, [%4];"
                 : "=r"(r[0]), "=r"(r[1]), "=r"(r[2]), "=r"(r[3]) : "r"(a));
}
__device__ __forceinline__ void hmma(float* d, const uint32_t* a, const uint32_t* b) {
    asm volatile("mma.sync.aligned.m16n8k16.row.col.f32.bf16.bf16.f32 "
                 "{%0,%1,%2,%3}, {%4,%5,%6,%7}, {%8,%9}, {%0,%1,%2,%3};"
                 : "+f"(d[0]), "+f"(d[1]), "+f"(d[2]), "+f"(d[3])
                 : "r"(a[0]), "r"(a[1]), "r"(a[2]), "r"(a[3]), "r"(b[0]), "r"(b[1]));
}
__device__ __forceinline__ unsigned short bf16u(float v) {
    return __bfloat16_as_ushort(__float2bfloat16(v));
}

// Gathered GEMM via mma.sync bf16 hi/lo split.
// 3-stage A ring (cp.async, coalesced cooperative gather, XOR-chunk swizzle),
// 8-slot index ring streamed from transposed nbrT, W fragments via __ldg (L2),
// fused deterministic BN stats. 4 CTAs/SM.
__global__ void __launch_bounds__(128, 4)
conv_mma(const uint32_t* __restrict__ xp, const int* __restrict__ nbrT,
         const uint32_t* __restrict__ wimg, float* __restrict__ outp, int n)
{
    extern __shared__ __align__(1024) char smraw[];
    const uint32_t sb = (uint32_t)__cvta_generic_to_shared(smraw);
    const int t = threadIdx.x, w = t >> 5, l = t & 31, base = blockIdx.x * TM;
    const int q = t & 7, rg = t >> 3;

    // idx cp.async: 128 ints per offset k into ring slot k&7
    auto idxcpa = [&](int k) {
        if (k < KNB && t < 32)
            cpa16s(sb + SM_IDX + (k & 7) * 512 + t * 16,
                   nbrT + (size_t)k * NPAD + base + t * 4);
    };
    // A gather for offset k into stage s (8 lanes cooperate per 128B row)
    auto gatherA = [&](int s, int k) {
        const int* id = (const int*)(smraw + SM_IDX + (k & 7) * 512);
        const uint32_t ab = sb + s * 16384;
        #pragma unroll
        for (int p = 0; p < 8; p++) {
            int r = rg + p * 16;
            unsigned g = (unsigned)id[r];
            if (g >= (unsigned)n) g = 0;
            cpa16s(ab + r * 128 + ((q ^ (r & 7)) << 4),
                   xp + (size_t)g * 32 + q * 4);
        }
    };

    // prologue: idx[0..3], then G0={A0,idx4}, G1={A1,idx5}
    idxcpa(0); idxcpa(1); idxcpa(2); idxcpa(3);
    asm volatile("cp.async.commit_group;" ::: "memory");
    asm volatile("cp.async.wait_group 0;" ::: "memory");
    __syncthreads();
    gatherA(0, 0); idxcpa(4);
    asm volatile("cp.async.commit_group;" ::: "memory");
    gatherA(1, 1); idxcpa(5);
    asm volatile("cp.async.commit_group;" ::: "memory");

    float df[2][4][4];
    #pragma unroll
    for (int mt = 0; mt < 2; mt++)
        #pragma unroll
        for (int nt = 0; nt < 4; nt++)
            #pragma unroll
            for (int e = 0; e < 4; e++) df[mt][nt][e] = 0.f;

    #pragma unroll 1
    for (int k = 0; k < KNB; k++) {
        if (k + 1 < KNB) asm volatile("cp.async.wait_group 1;" ::: "memory");
        else             asm volatile("cp.async.wait_group 0;" ::: "memory");
        __syncthreads();                      // stage k visible; prev compute done
        if (k + 2 < KNB) {
            gatherA((k + 2) % 3, k + 2); idxcpa(k + 6);
            asm volatile("cp.async.commit_group;" ::: "memory");
        }

        const uint32_t ab = sb + (k % 3) * 16384;
        uint32_t af[2][2][2][4];              // [img][mt][kt][4]
        #pragma unroll
        for (int img = 0; img < 2; img++)
            #pragma unroll
            for (int mt = 0; mt < 2; mt++)
                #pragma unroll
                for (int kt = 0; kt < 2; kt++) {
                    int row = w * 32 + mt * 16 + (l & 15);
                    int ch  = img * 4 + kt * 2 + (l >> 4);
                    ldm4(af[img][mt][kt], ab + row * 128 + ((ch ^ (row & 7)) << 4));
                }

        const uint4* wq = (const uint4*)(wimg + (size_t)k * 1024);
        uint32_t bh[2][4][2], bl[2][4][2];    // [kt][nt][2]
        #pragma unroll
        for (int j = 0; j < 4; j++) {         // hi image fragments
            uint4 v = __ldg(&wq[j * 32 + l]);
            int f0 = 2 * j, f1 = 2 * j + 1;
            bh[(f0 >> 2) & 1][f0 & 3][0] = v.x;  bh[(f0 >> 2) & 1][f0 & 3][1] = v.y;
            bh[(f1 >> 2) & 1][f1 & 3][0] = v.z;  bh[(f1 >> 2) & 1][f1 & 3][1] = v.w;
        }
        #pragma unroll
        for (int j = 4; j < 8; j++) {         // lo image fragments
            uint4 v = __ldg(&wq[j * 32 + l]);
            int f0 = 2 * j - 8, f1 = 2 * j - 7;
            bl[(f0 >> 2) & 1][f0 & 3][0] = v.x;  bl[(f0 >> 2) & 1][f0 & 3][1] = v.y;
            bl[(f1 >> 2) & 1][f1 & 3][0] = v.z;  bl[(f1 >> 2) & 1][f1 & 3][1] = v.w;
        }

        #pragma unroll
        for (int mt = 0; mt < 2; mt++)
            #pragma unroll
            for (int nt = 0; nt < 4; nt++)
                #pragma unroll
                for (int kt = 0; kt < 2; kt++) {
                    hmma(df[mt][nt], af[0][mt][kt], bh[kt][nt]);   // hi*Wh
                    hmma(df[mt][nt], af[1][mt][kt], bh[kt][nt]);   // lo*Wh
                    hmma(df[mt][nt], af[0][mt][kt], bl[kt][nt]);   // hi*Wl
                }
    }

    const int g2 = l >> 2, tc = (l & 3) * 2;
    #pragma unroll
    for (int mt = 0; mt < 2; mt++)
        #pragma unroll
        for (int nt = 0; nt < 4; nt++) {
            int r0 = base + w * 32 + mt * 16 + g2;
            int c  = nt * 8 + tc;
            if (r0 < n)
                *(float2*)(outp + (size_t)r0 * CH + c) = make_float2(df[mt][nt][0], df[mt][nt][1]);
            if (r0 + 8 < n)
                *(float2*)(outp + (size_t)(r0 + 8) * CH + c) = make_float2(df[mt][nt][2], df[mt][nt][3]);
        }

    // fused BN stats (deterministic)
    __syncthreads();
    float* ssum = (float*)smraw;              // 128*33
    float* ssq  = (float*)(smraw + 16896);
    #pragma unroll
    for (int mt = 0; mt < 2; mt++)
        #pragma unroll
        for (int nt = 0; nt < 4; nt++) {
            int rl = w * 32 + mt * 16 + g2;
            int c  = nt * 8 + tc;
            bool v0 = (base + rl) < n, v1 = (base + rl + 8) < n;
            float a = v0 ? df[mt][nt][0] : 0.f, b = v0 ? df[mt][nt][1] : 0.f;
            float cc = v1 ? df[mt][nt][2] : 0.f, dd = v1 ? df[mt][nt][3] : 0.f;
            ssum[rl * 33 + c] = a;        ssum[rl * 33 + c + 1] = b;
            ssum[(rl + 8) * 33 + c] = cc; ssum[(rl + 8) * 33 + c + 1] = dd;
            ssq[rl * 33 + c] = a * a;        ssq[rl * 33 + c + 1] = b * b;
            ssq[(rl + 8) * 33 + c] = cc * cc; ssq[(rl + 8) * 33 + c + 1] = dd * dd;
        }
    __syncthreads();
    if (t < 32) {
        float s = 0.f, q2 = 0.f;
        for (int i = 0; i < TM; i++) { s += ssum[i * 33 + t]; q2 += ssq[i * 33 + t]; }
        g_part[(size_t)blockIdx.x * 64 + t]      = s;
        g_part[(size_t)blockIdx.x * 64 + 32 + t] = q2;
    }
}

// Transpose neighbors: nbrT[k][r] = nbr[r][k] (coalesced writes per k)
__global__ void ntrans(const int* __restrict__ nbr, int* __restrict__ nbrT, int n)
{
    int j = blockIdx.x * blockDim.x + threadIdx.x;
    int stride = gridDim.x * blockDim.x;
    for (int r = j; r < n; r += stride) {
        #pragma unroll
        for (int k = 0; k < KNB; k++)
            nbrT[(size_t)k * NPAD + r] = nbr[(size_t)r * KNB + k];
    }
}

// Pack W[k][ci][co] fp32 -> per-k B-fragment-ordered bf16 hi/lo image.
__global__ void wprep(const float* __restrict__ W, uint32_t* __restrict__ img)
{
    int i = blockIdx.x * blockDim.x + threadIdx.x;
    if (i >= KNB * 1024) return;
    int k = i >> 10, rem = i & 1023;
    int j = rem >> 7, lr = rem & 127, lane = lr >> 2, s = lr & 3;
    int f = 2 * j + (s >> 1), r = s & 1;
    int im = f >> 3, kt = (f >> 2) & 1, nt = f & 3;
    int ci0 = kt * 16 + r * 8 + (lane & 3) * 2;
    int co  = nt * 8 + (lane >> 2);
    float v0 = W[k * 1024 + ci0 * 32 + co];
    float v1 = W[k * 1024 + (ci0 + 1) * 32 + co];
    unsigned short p0, p1;
    if (im == 0) { p0 = bf16u(v0); p1 = bf16u(v1); }
    else {
        p0 = bf16u(v0 - __bfloat162float(__ushort_as_bfloat16(bf16u(v0))));
        p1 = bf16u(v1 - __bfloat162float(__ushort_as_bfloat16(bf16u(v1))));
    }
    img[i] = (uint32_t)p0 | ((uint32_t)p1 << 16);
}

__global__ void xprep(const float* __restrict__ x, uint32_t* __restrict__ xp, int n)
{
    int j = blockIdx.x * blockDim.x + threadIdx.x;
    int total = n * 16, stride = gridDim.x * blockDim.x;
    for (int i = j; i < total; i += stride) {
        int row = i >> 4, wp = i & 15;
        float2 v = *(const float2*)(x + (size_t)row * 32 + wp * 2);
        unsigned short h0 = bf16u(v.x), h1 = bf16u(v.y);
        float l0 = v.x - __bfloat162float(__ushort_as_bfloat16(h0));
        float l1 = v.y - __bfloat162float(__ushort_as_bfloat16(h1));
        xp[(size_t)row * 32 + wp]      = (uint32_t)h0 | ((uint32_t)h1 << 16);
        xp[(size_t)row * 32 + 16 + wp] = (uint32_t)bf16u(l0) | ((uint32_t)bf16u(l1) << 16);
    }
}

__global__ void bnreluprep(const float* __restrict__ x, uint32_t* __restrict__ xp, int n)
{
    int j = blockIdx.x * blockDim.x + threadIdx.x;
    int total = n * 16, stride = gridDim.x * blockDim.x;
    int wp0 = j & 15;
    float sc0 = g_bn[2 * wp0], sc1 = g_bn[2 * wp0 + 1];
    float sh0 = g_bn[32 + 2 * wp0], sh1 = g_bn[33 + 2 * wp0];
    for (int i = j; i < total; i += stride) {
        int row = i >> 4, wp = i & 15;
        float2 v = *(const float2*)(x + (size_t)row * 32 + wp * 2);
        float a = fmaxf(v.x * sc0 + sh0, 0.f);
        float b = fmaxf(v.y * sc1 + sh1, 0.f);
        unsigned short h0 = bf16u(a), h1 = bf16u(b);
        float l0 = a - __bfloat162float(__ushort_as_bfloat16(h0));
        float l1 = b - __bfloat162float(__ushort_as_bfloat16(h1));
        xp[(size_t)row * 32 + wp]      = (uint32_t)h0 | ((uint32_t)h1 << 16);
        xp[(size_t)row * 32 + 16 + wp] = (uint32_t)bf16u(l0) | ((uint32_t)bf16u(l1) << 16);
    }
}

__global__ void reduce_kernel(const float* __restrict__ gamma,
                              const float* __restrict__ beta, int n, int nblk)
{
    __shared__ double sd[512];
    __shared__ double comb[64];
    const int t = threadIdx.x;
    const int c = t & 63, s = t >> 6;
    double acc = 0.0;
    for (int i = s; i < nblk; i += 8) acc += (double)g_part[(size_t)i * 64 + c];
    sd[t] = acc;
    __syncthreads();
    if (t < 64) {
        double a = 0.0;
        #pragma unroll
        for (int s2 = 0; s2 < 8; s2++) a += sd[t + 64 * s2];
        comb[t] = a;
    }
    __syncthreads();
    if (t < 32) {
        double mean = comb[t] / (double)n;
        double var  = comb[32 + t] / (double)n - mean * mean;
        float sc = (float)((double)gamma[t] / sqrt(var + 1e-4));
        float sh = (float)((double)beta[t] - mean * (double)sc);
        g_bn[t] = sc; g_bn[32 + t] = sh;
    }
}

__global__ void final_kernel(float* __restrict__ out, const float* __restrict__ feat, int n)
{
    int j = blockIdx.x * blockDim.x + threadIdx.x;
    int total = n * 8, stride = gridDim.x * blockDim.x;
    int m = j & 7;
    float4 sc = *(const float4*)(g_bn + m * 4);
    float4 sh = *(const float4*)(g_bn + 32 + m * 4);
    float4* o4 = (float4*)out;
    const float4* f4 = (const float4*)feat;
    for (int i = j; i < total; i += stride) {
        float4 v = o4[i], f = f4[i];
        v.x = fmaxf(v.x * sc.x + sh.x + f.x, 0.f);
        v.y = fmaxf(v.y * sc.y + sh.y + f.y, 0.f);
        v.z = fmaxf(v.z * sc.z + sh.z + f.z, 0.f);
        v.w = fmaxf(v.w * sc.w + sh.w + f.w, 0.f);
        o4[i] = v;
    }
}

extern "C" void kernel_launch(void* const* d_in, const int* in_sizes, int n_in,
                              void* d_out, int out_size)
{
    const float* feat = (const float*)d_in[0];
    const int*   nbr  = (const int*)  d_in[1];
    const float* W1   = (const float*)d_in[2];
    const float* g1   = (const float*)d_in[3];
    const float* b1   = (const float*)d_in[4];
    const float* W2   = (const float*)d_in[5];
    const float* g2   = (const float*)d_in[6];
    const float* b2   = (const float*)d_in[7];
    int n = in_sizes[0] / CH;
    float* out = (float*)d_out;

    float *h1, *xpf, *h1pf;
    uint32_t *w1i, *w2i;
    int* nbrT;
    cudaGetSymbolAddress((void**)&h1,   g_h1);
    cudaGetSymbolAddress((void**)&xpf,  g_xp);
    cudaGetSymbolAddress((void**)&h1pf, g_h1p);
    cudaGetSymbolAddress((void**)&w1i,  g_w1img);
    cudaGetSymbolAddress((void**)&w2i,  g_w2img);
    cudaGetSymbolAddress((void**)&nbrT, g_nbrT);

    cudaFuncSetAttribute(conv_mma, cudaFuncAttributeMaxDynamicSharedMemorySize, SM_TOT);
    int grid = (n + TM - 1) / TM;

    ntrans<<<2048, 256>>>(nbr, nbrT, n);
    wprep<<<(KNB * 1024 + 255) / 256, 256>>>(W1, w1i);
    wprep<<<(KNB * 1024 + 255) / 256, 256>>>(W2, w2i);
    xprep<<<2048, 256>>>(feat, (uint32_t*)xpf, n);
    conv_mma<<<grid, 128, SM_TOT>>>((const uint32_t*)xpf, nbrT, w1i, h1, n);
    reduce_kernel<<<1, 512>>>(g1, b1, n, grid);
    bnreluprep<<<2048, 256>>>(h1, (uint32_t*)h1pf, n);
    conv_mma<<<grid, 128, SM_TOT>>>((const uint32_t*)h1pf, nbrT, w2i, out, n);
    reduce_kernel<<<1, 512>>>(g2, b2, n, grid);
    final_kernel<<<2048, 256>>>(out, feat, n);
}

// round 16
// speedup vs baseline: 1.0191x; 1.0191x over previous
#include <cuda_runtime.h>
#include <cuda_bf16.h>
#include <cstdint>

#define CH 32
#define KNB 27
#define TM 128
#define NPAD 2000128
#define SM_IDX 49152
#define SM_TOT 53248

__device__ __align__(128) uint32_t g_xp [(size_t)NPAD * 32];
__device__ __align__(128) uint32_t g_h1p[(size_t)NPAD * 32];
__device__ __align__(128) float    g_h1 [(size_t)NPAD * 32];
__device__ __align__(128) int      g_nbrT[(size_t)KNB * NPAD];
__device__ __align__(128) uint32_t g_w1img[KNB * 1024];
__device__ __align__(128) uint32_t g_w2img[KNB * 1024];
__device__ float g_part[15700 * 64];
__device__ float g_bn[64];

__device__ __forceinline__ void cpa16s(uint32_t d, const void* s) {
    asm volatile("cp.async.cg.shared.global [%0], [%1], 16;" :: "r"(d), "l"(s));
}
__device__ __forceinline__ void ldm4(uint32_t* r, uint32_t a) {
    asm volatile("ldmatrix.sync.aligned.m8n8.x4.shared.b16 {%0,%1,%2,%3}, [%4];"
                 : "=r"(r[0]), "=r"(r[1]), "=r"(r[2]), "=r"(r[3]) : "r"(a));
}
__device__ __forceinline__ void hmma(float* d, const uint32_t* a, const uint32_t* b) {
    asm volatile("mma.sync.aligned.m16n8k16.row.col.f32.bf16.bf16.f32 "
                 "{%0,%1,%2,%3}, {%4,%5,%6,%7}, {%8,%9}, {%0,%1,%2,%3};"
                 : "+f"(d[0]), "+f"(d[1]), "+f"(d[2]), "+f"(d[3])
                 : "r"(a[0]), "r"(a[1]), "r"(a[2]), "r"(a[3]), "r"(b[0]), "r"(b[1]));
}
__device__ __forceinline__ unsigned short bf16u(float v) {
    return __bfloat16_as_ushort(__float2bfloat16(v));
}

// Gathered GEMM via mma.sync bf16 hi/lo split — WARP-AUTONOMOUS pipelines.
// Each warp owns 32 rows: private 3-stage A ring (4KB/stage), private idx ring,
// per-warp cp.async groups, __syncwarp only (no CTA barrier in mainloop).
__global__ void __launch_bounds__(128, 4)
conv_mma(const uint32_t* __restrict__ xp, const int* __restrict__ nbrT,
         const uint32_t* __restrict__ wimg, float* __restrict__ outp, int n)
{
    extern __shared__ __align__(1024) char smraw[];
    const uint32_t sb = (uint32_t)__cvta_generic_to_shared(smraw);
    const int t = threadIdx.x, w = t >> 5, l = t & 31, base = blockIdx.x * TM;
    const int q = l & 7, rg2 = l >> 3;          // chunk, row-subgroup (0..3)
    const uint32_t aw = sb + w * 12288;         // warp A ring (3 x 4096)
    const uint32_t iw = sb + SM_IDX + w * 1024; // warp idx ring (8 x 128)
    const int wrow = w * 32;

    // idx for offset k: warp's 32 ints (128B), lanes 0-7
    auto idxcpa = [&](int k) {
        if (k < KNB && l < 8)
            cpa16s(iw + (k & 7) * 128 + l * 16,
                   nbrT + (size_t)k * NPAD + base + wrow + l * 4);
    };
    // gather offset k into warp-private stage s (8 lanes per 128B row)
    auto gatherA = [&](int s, int k) {
        const int* id = (const int*)(smraw + SM_IDX + w * 1024 + (k & 7) * 128);
        const uint32_t ab = aw + s * 4096;
        #pragma unroll
        for (int p = 0; p < 8; p++) {
            int r = rg2 + p * 4;                // 0..31 (warp-local)
            unsigned g = (unsigned)id[r];
            if (g >= (unsigned)n) g = 0;
            cpa16s(ab + r * 128 + ((q ^ (r & 7)) << 4),
                   xp + (size_t)g * 32 + q * 4);
        }
    };

    // per-warp prologue
    idxcpa(0); idxcpa(1); idxcpa(2); idxcpa(3);
    asm volatile("cp.async.commit_group;" ::: "memory");
    asm volatile("cp.async.wait_group 0;" ::: "memory");
    __syncwarp();
    gatherA(0, 0); idxcpa(4);
    asm volatile("cp.async.commit_group;" ::: "memory");
    gatherA(1, 1); idxcpa(5);
    asm volatile("cp.async.commit_group;" ::: "memory");

    float df[2][4][4];
    #pragma unroll
    for (int mt = 0; mt < 2; mt++)
        #pragma unroll
        for (int nt = 0; nt < 4; nt++)
            #pragma unroll
            for (int e = 0; e < 4; e++) df[mt][nt][e] = 0.f;

    #pragma unroll 1
    for (int k = 0; k < KNB; k++) {
        if (k + 1 < KNB) asm volatile("cp.async.wait_group 1;" ::: "memory");
        else             asm volatile("cp.async.wait_group 0;" ::: "memory");
        __syncwarp();   // cross-lane visibility of stage k; orders k-1 reads before k+2 writes
        if (k + 2 < KNB) {
            gatherA((k + 2) % 3, k + 2); idxcpa(k + 6);
            asm volatile("cp.async.commit_group;" ::: "memory");
        }

        const uint32_t ab = aw + (k % 3) * 4096;
        uint32_t af[2][2][2][4];                // [img][mt][kt][4]
        #pragma unroll
        for (int img = 0; img < 2; img++)
            #pragma unroll
            for (int mt = 0; mt < 2; mt++)
                #pragma unroll
                for (int kt = 0; kt < 2; kt++) {
                    int r  = mt * 16 + (l & 15);            // warp-local row
                    int ch = img * 4 + kt * 2 + (l >> 4);
                    ldm4(af[img][mt][kt], ab + r * 128 + ((ch ^ (r & 7)) << 4));
                }

        const uint4* wq = (const uint4*)(wimg + (size_t)k * 1024);
        uint32_t bh[2][4][2], bl[2][4][2];      // [kt][nt][2]
        #pragma unroll
        for (int j = 0; j < 4; j++) {           // hi image fragments
            uint4 v = __ldg(&wq[j * 32 + l]);
            int f0 = 2 * j, f1 = 2 * j + 1;
            bh[(f0 >> 2) & 1][f0 & 3][0] = v.x;  bh[(f0 >> 2) & 1][f0 & 3][1] = v.y;
            bh[(f1 >> 2) & 1][f1 & 3][0] = v.z;  bh[(f1 >> 2) & 1][f1 & 3][1] = v.w;
        }
        #pragma unroll
        for (int j = 4; j < 8; j++) {           // lo image fragments
            uint4 v = __ldg(&wq[j * 32 + l]);
            int f0 = 2 * j - 8, f1 = 2 * j - 7;
            bl[(f0 >> 2) & 1][f0 & 3][0] = v.x;  bl[(f0 >> 2) & 1][f0 & 3][1] = v.y;
            bl[(f1 >> 2) & 1][f1 & 3][0] = v.z;  bl[(f1 >> 2) & 1][f1 & 3][1] = v.w;
        }

        #pragma unroll
        for (int mt = 0; mt < 2; mt++)
            #pragma unroll
            for (int nt = 0; nt < 4; nt++)
                #pragma unroll
                for (int kt = 0; kt < 2; kt++) {
                    hmma(df[mt][nt], af[0][mt][kt], bh[kt][nt]);   // hi*Wh
                    hmma(df[mt][nt], af[1][mt][kt], bh[kt][nt]);   // lo*Wh
                    hmma(df[mt][nt], af[0][mt][kt], bl[kt][nt]);   // hi*Wl
                }
    }

    const int g2 = l >> 2, tc = (l & 3) * 2;
    #pragma unroll
    for (int mt = 0; mt < 2; mt++)
        #pragma unroll
        for (int nt = 0; nt < 4; nt++) {
            int r0 = base + wrow + mt * 16 + g2;
            int c  = nt * 8 + tc;
            if (r0 < n)
                *(float2*)(outp + (size_t)r0 * CH + c) = make_float2(df[mt][nt][0], df[mt][nt][1]);
            if (r0 + 8 < n)
                *(float2*)(outp + (size_t)(r0 + 8) * CH + c) = make_float2(df[mt][nt][2], df[mt][nt][3]);
        }

    // fused BN stats (deterministic) — only CTA barrier in the kernel
    __syncthreads();
    float* ssum = (float*)smraw;                // 128*33
    float* ssq  = (float*)(smraw + 16896);
    #pragma unroll
    for (int mt = 0; mt < 2; mt++)
        #pragma unroll
        for (int nt = 0; nt < 4; nt++) {
            int rl = wrow + mt * 16 + g2;
            int c  = nt * 8 + tc;
            bool v0 = (base + rl) < n, v1 = (base + rl + 8) < n;
            float a = v0 ? df[mt][nt][0] : 0.f, b = v0 ? df[mt][nt][1] : 0.f;
            float cc = v1 ? df[mt][nt][2] : 0.f, dd = v1 ? df[mt][nt][3] : 0.f;
            ssum[rl * 33 + c] = a;        ssum[rl * 33 + c + 1] = b;
            ssum[(rl + 8) * 33 + c] = cc; ssum[(rl + 8) * 33 + c + 1] = dd;
            ssq[rl * 33 + c] = a * a;        ssq[rl * 33 + c + 1] = b * b;
            ssq[(rl + 8) * 33 + c] = cc * cc; ssq[(rl + 8) * 33 + c + 1] = dd * dd;
        }
    __syncthreads();
    if (t < 32) {
        float s = 0.f, q2 = 0.f;
        for (int i = 0; i < TM; i++) { s += ssum[i * 33 + t]; q2 += ssq[i * 33 + t]; }
        g_part[(size_t)blockIdx.x * 64 + t]      = s;
        g_part[(size_t)blockIdx.x * 64 + 32 + t] = q2;
    }
}

// Transpose neighbors: nbrT[k][r] = nbr[r][k]
__global__ void ntrans(const int* __restrict__ nbr, int* __restrict__ nbrT, int n)
{
    int j = blockIdx.x * blockDim.x + threadIdx.x;
    int stride = gridDim.x * blockDim.x;
    for (int r = j; r < n; r += stride) {
        #pragma unroll
        for (int k = 0; k < KNB; k++)
            nbrT[(size_t)k * NPAD + r] = nbr[(size_t)r * KNB + k];
    }
}

// Pack W[k][ci][co] fp32 -> per-k B-fragment-ordered bf16 hi/lo image.
__global__ void wprep(const float* __restrict__ W, uint32_t* __restrict__ img)
{
    int i = blockIdx.x * blockDim.x + threadIdx.x;
    if (i >= KNB * 1024) return;
    int k = i >> 10, rem = i & 1023;
    int j = rem >> 7, lr = rem & 127, lane = lr >> 2, s = lr & 3;
    int f = 2 * j + (s >> 1), r = s & 1;
    int im = f >> 3, kt = (f >> 2) & 1, nt = f & 3;
    int ci0 = kt * 16 + r * 8 + (lane & 3) * 2;
    int co  = nt * 8 + (lane >> 2);
    float v0 = W[k * 1024 + ci0 * 32 + co];
    float v1 = W[k * 1024 + (ci0 + 1) * 32 + co];
    unsigned short p0, p1;
    if (im == 0) { p0 = bf16u(v0); p1 = bf16u(v1); }
    else {
        p0 = bf16u(v0 - __bfloat162float(__ushort_as_bfloat16(bf16u(v0))));
        p1 = bf16u(v1 - __bfloat162float(__ushort_as_bfloat16(bf16u(v1))));
    }
    img[i] = (uint32_t)p0 | ((uint32_t)p1 << 16);
}

__global__ void xprep(const float* __restrict__ x, uint32_t* __restrict__ xp, int n)
{
    int j = blockIdx.x * blockDim.x + threadIdx.x;
    int total = n * 16, stride = gridDim.x * blockDim.x;
    for (int i = j; i < total; i += stride) {
        int row = i >> 4, wp = i & 15;
        float2 v = *(const float2*)(x + (size_t)row * 32 + wp * 2);
        unsigned short h0 = bf16u(v.x), h1 = bf16u(v.y);
        float l0 = v.x - __bfloat162float(__ushort_as_bfloat16(h0));
        float l1 = v.y - __bfloat162float(__ushort_as_bfloat16(h1));
        xp[(size_t)row * 32 + wp]      = (uint32_t)h0 | ((uint32_t)h1 << 16);
        xp[(size_t)row * 32 + 16 + wp] = (uint32_t)bf16u(l0) | ((uint32_t)bf16u(l1) << 16);
    }
}

__global__ void bnreluprep(const float* __restrict__ x, uint32_t* __restrict__ xp, int n)
{
    int j = blockIdx.x * blockDim.x + threadIdx.x;
    int total = n * 16, stride = gridDim.x * blockDim.x;
    int wp0 = j & 15;
    float sc0 = g_bn[2 * wp0], sc1 = g_bn[2 * wp0 + 1];
    float sh0 = g_bn[32 + 2 * wp0], sh1 = g_bn[33 + 2 * wp0];
    for (int i = j; i < total; i += stride) {
        int row = i >> 4, wp = i & 15;
        float2 v = *(const float2*)(x + (size_t)row * 32 + wp * 2);
        float a = fmaxf(v.x * sc0 + sh0, 0.f);
        float b = fmaxf(v.y * sc1 + sh1, 0.f);
        unsigned short h0 = bf16u(a), h1 = bf16u(b);
        float l0 = a - __bfloat162float(__ushort_as_bfloat16(h0));
        float l1 = b - __bfloat162float(__ushort_as_bfloat16(h1));
        xp[(size_t)row * 32 + wp]      = (uint32_t)h0 | ((uint32_t)h1 << 16);
        xp[(size_t)row * 32 + 16 + wp] = (uint32_t)bf16u(l0) | ((uint32_t)bf16u(l1) << 16);
    }
}

__global__ void reduce_kernel(const float* __restrict__ gamma,
                              const float* __restrict__ beta, int n, int nblk)
{
    __shared__ double sd[512];
    __shared__ double comb[64];
    const int t = threadIdx.x;
    const int c = t & 63, s = t >> 6;
    double acc = 0.0;
    for (int i = s; i < nblk; i += 8) acc += (double)g_part[(size_t)i * 64 + c];
    sd[t] = acc;
    __syncthreads();
    if (t < 64) {
        double a = 0.0;
        #pragma unroll
        for (int s2 = 0; s2 < 8; s2++) a += sd[t + 64 * s2];
        comb[t] = a;
    }
    __syncthreads();
    if (t < 32) {
        double mean = comb[t] / (double)n;
        double var  = comb[32 + t] / (double)n - mean * mean;
        float sc = (float)((double)gamma[t] / sqrt(var + 1e-4));
        float sh = (float)((double)beta[t] - mean * (double)sc);
        g_bn[t] = sc; g_bn[32 + t] = sh;
    }
}

__global__ void final_kernel(float* __restrict__ out, const float* __restrict__ feat, int n)
{
    int j = blockIdx.x * blockDim.x + threadIdx.x;
    int total = n * 8, stride = gridDim.x * blockDim.x;
    int m = j & 7;
    float4 sc = *(const float4*)(g_bn + m * 4);
    float4 sh = *(const float4*)(g_bn + 32 + m * 4);
    float4* o4 = (float4*)out;
    const float4* f4 = (const float4*)feat;
    for (int i = j; i < total; i += stride) {
        float4 v = o4[i], f = f4[i];
        v.x = fmaxf(v.x * sc.x + sh.x + f.x, 0.f);
        v.y = fmaxf(v.y * sc.y + sh.y + f.y, 0.f);
        v.z = fmaxf(v.z * sc.z + sh.z + f.z, 0.f);
        v.w = fmaxf(v.w * sc.w + sh.w + f.w, 0.f);
        o4[i] = v;
    }
}

extern "C" void kernel_launch(void* const* d_in, const int* in_sizes, int n_in,
                              void* d_out, int out_size)
{
    const float* feat = (const float*)d_in[0];
    const int*   nbr  = (const int*)  d_in[1];
    const float* W1   = (const float*)d_in[2];
    const float* g1   = (const float*)d_in[3];
    const float* b1   = (const float*)d_in[4];
    const float* W2   = (const float*)d_in[5];
    const float* g2   = (const float*)d_in[6];
    const float* b2   = (const float*)d_in[7];
    int n = in_sizes[0] / CH;
    float* out = (float*)d_out;

    float *h1, *xpf, *h1pf;
    uint32_t *w1i, *w2i;
    int* nbrT;
    cudaGetSymbolAddress((void**)&h1,   g_h1);
    cudaGetSymbolAddress((void**)&xpf,  g_xp);
    cudaGetSymbolAddress((void**)&h1pf, g_h1p);
    cudaGetSymbolAddress((void**)&w1i,  g_w1img);
    cudaGetSymbolAddress((void**)&w2i,  g_w2img);
    cudaGetSymbolAddress((void**)&nbrT, g_nbrT);

    cudaFuncSetAttribute(conv_mma, cudaFuncAttributeMaxDynamicSharedMemorySize, SM_TOT);
    int grid = (n + TM - 1) / TM;

    ntrans<<<2048, 256>>>(nbr, nbrT, n);
    wprep<<<(KNB * 1024 + 255) / 256, 256>>>(W1, w1i);
    wprep<<<(KNB * 1024 + 255) / 256, 256>>>(W2, w2i);
    xprep<<<2048, 256>>>(feat, (uint32_t*)xpf, n);
    conv_mma<<<grid, 128, SM_TOT>>>((const uint32_t*)xpf, nbrT, w1i, h1, n);
    reduce_kernel<<<1, 512>>>(g1, b1, n, grid);
    bnreluprep<<<2048, 256>>>(h1, (uint32_t*)h1pf, n);
    conv_mma<<<grid, 128, SM_TOT>>>((const uint32_t*)h1pf, nbrT, w2i, out, n);
    reduce_kernel<<<1, 512>>>(g2, b2, n, grid);
    final_kernel<<<2048, 256>>>(out, feat, n);
}

// round 17
// speedup vs baseline: 1.2432x; 1.2198x over previous
#include <cuda_runtime.h>
#include <cuda_fp16.h>
#include <cuda_bf16.h>
#include <cstdint>

#define CH 32
#define KNB 27
#define TM 128
#define NPAD 2000128
#define SM_IDX 24576
#define SM_TOT 33792

__device__ __align__(128) uint32_t g_xp [(size_t)NPAD * 16];   // fp16 rows, 64B
__device__ __align__(128) uint32_t g_h1p[(size_t)NPAD * 16];
__device__ __align__(128) float    g_h1 [(size_t)NPAD * 32];
__device__ __align__(128) int      g_nbrT[(size_t)KNB * NPAD];
__device__ __align__(128) uint32_t g_w1img[KNB * 1024];        // fp16 hi/lo fragment images
__device__ __align__(128) uint32_t g_w2img[KNB * 1024];
__device__ float g_part[15700 * 64];
__device__ float g_bn[64];

__device__ __forceinline__ void cpa16s(uint32_t d, const void* s) {
    asm volatile("cp.async.cg.shared.global [%0], [%1], 16;" :: "r"(d), "l"(s));
}
__device__ __forceinline__ void ldm4(uint32_t* r, uint32_t a) {
    asm volatile("ldmatrix.sync.aligned.m8n8.x4.shared.b16 {%0,%1,%2,%3}, [%4];"
                 : "=r"(r[0]), "=r"(r[1]), "=r"(r[2]), "=r"(r[3]) : "r"(a));
}
__device__ __forceinline__ void hmma(float* d, const uint32_t* a, const uint32_t* b) {
    asm volatile("mma.sync.aligned.m16n8k16.row.col.f32.f16.f16.f32 "
                 "{%0,%1,%2,%3}, {%4,%5,%6,%7}, {%8,%9}, {%0,%1,%2,%3};"
                 : "+f"(d[0]), "+f"(d[1]), "+f"(d[2]), "+f"(d[3])
                 : "r"(a[0]), "r"(a[1]), "r"(a[2]), "r"(a[3]), "r"(b[0]), "r"(b[1]));
}
__device__ __forceinline__ unsigned short f16u(float v) {
    return __half_as_ushort(__float2half_rn(v));
}

// Gathered GEMM, fp16 x (64B rows) x fp16 W hi/lo, warp-autonomous pipelines.
// Each warp: 32 rows, private 3-stage A ring (2KB/stage), private idx ring,
// per-warp cp.async groups, __syncwarp-only mainloop. Fused BN stats.
__global__ void __launch_bounds__(128, 5)
conv_mma(const uint32_t* __restrict__ xp, const int* __restrict__ nbrT,
         const uint32_t* __restrict__ wimg, float* __restrict__ outp, int n)
{
    extern __shared__ __align__(1024) char smraw[];
    const uint32_t sb = (uint32_t)__cvta_generic_to_shared(smraw);
    const int t = threadIdx.x, w = t >> 5, l = t & 31, base = blockIdx.x * TM;
    const uint32_t aw = sb + w * 6144;          // warp A ring (3 x 2048)
    const uint32_t iw = sb + SM_IDX + w * 1024; // warp idx ring (8 x 128)
    const int wrow = w * 32;

    auto idxcpa = [&](int k) {
        if (k < KNB && l < 8)
            cpa16s(iw + (k & 7) * 128 + l * 16,
                   nbrT + (size_t)k * NPAD + base + wrow + l * 4);
    };
    // gather offset k into warp stage s: 4 lanes per 64B row, swizzle c^((r>>1)&3)
    auto gatherA = [&](int s, int k) {
        const int* id = (const int*)(smraw + SM_IDX + w * 1024 + (k & 7) * 128);
        const uint32_t ab = aw + s * 2048;
        const int q = l & 3, rr = l >> 2;
        #pragma unroll
        for (int p = 0; p < 4; p++) {
            int r = rr + p * 8;                 // warp-local row 0..31
            unsigned g = (unsigned)id[r];
            if (g >= (unsigned)n) g = 0;
            cpa16s(ab + r * 64 + ((q ^ ((r >> 1) & 3)) << 4),
                   xp + (size_t)g * 16 + q * 4);
        }
    };

    idxcpa(0); idxcpa(1); idxcpa(2); idxcpa(3);
    asm volatile("cp.async.commit_group;" ::: "memory");
    asm volatile("cp.async.wait_group 0;" ::: "memory");
    __syncwarp();
    gatherA(0, 0); idxcpa(4);
    asm volatile("cp.async.commit_group;" ::: "memory");
    gatherA(1, 1); idxcpa(5);
    asm volatile("cp.async.commit_group;" ::: "memory");

    float df[2][4][4];
    #pragma unroll
    for (int mt = 0; mt < 2; mt++)
        #pragma unroll
        for (int nt = 0; nt < 4; nt++)
            #pragma unroll
            for (int e = 0; e < 4; e++) df[mt][nt][e] = 0.f;

    #pragma unroll 1
    for (int k = 0; k < KNB; k++) {
        if (k + 1 < KNB) asm volatile("cp.async.wait_group 1;" ::: "memory");
        else             asm volatile("cp.async.wait_group 0;" ::: "memory");
        __syncwarp();
        if (k + 2 < KNB) {
            gatherA((k + 2) % 3, k + 2); idxcpa(k + 6);
            asm volatile("cp.async.commit_group;" ::: "memory");
        }

        const uint32_t ab = aw + (k % 3) * 2048;
        uint32_t af[2][2][4];                   // [mt][kt][4]
        #pragma unroll
        for (int mt = 0; mt < 2; mt++)
            #pragma unroll
            for (int kt = 0; kt < 2; kt++) {
                int r = mt * 16 + (l & 15);
                int c = kt * 2 + (l >> 4);      // 16B chunk 0..3
                ldm4(af[mt][kt], ab + r * 64 + ((c ^ ((r >> 1) & 3)) << 4));
            }

        const uint4* wq = (const uint4*)(wimg + (size_t)k * 1024);
        uint32_t bh[2][4][2], bl[2][4][2];      // [kt][nt][2]
        #pragma unroll
        for (int j = 0; j < 4; j++) {           // hi image fragments
            uint4 v = __ldg(&wq[j * 32 + l]);
            int f0 = 2 * j, f1 = 2 * j + 1;
            bh[(f0 >> 2) & 1][f0 & 3][0] = v.x;  bh[(f0 >> 2) & 1][f0 & 3][1] = v.y;
            bh[(f1 >> 2) & 1][f1 & 3][0] = v.z;  bh[(f1 >> 2) & 1][f1 & 3][1] = v.w;
        }
        #pragma unroll
        for (int j = 4; j < 8; j++) {           // lo image fragments
            uint4 v = __ldg(&wq[j * 32 + l]);
            int f0 = 2 * j - 8, f1 = 2 * j - 7;
            bl[(f0 >> 2) & 1][f0 & 3][0] = v.x;  bl[(f0 >> 2) & 1][f0 & 3][1] = v.y;
            bl[(f1 >> 2) & 1][f1 & 3][0] = v.z;  bl[(f1 >> 2) & 1][f1 & 3][1] = v.w;
        }

        #pragma unroll
        for (int mt = 0; mt < 2; mt++)
            #pragma unroll
            for (int nt = 0; nt < 4; nt++)
                #pragma unroll
                for (int kt = 0; kt < 2; kt++) {
                    hmma(df[mt][nt], af[mt][kt], bh[kt][nt]);   // x*Wh
                    hmma(df[mt][nt], af[mt][kt], bl[kt][nt]);   // x*Wl
                }
    }

    const int g2 = l >> 2, tc = (l & 3) * 2;
    #pragma unroll
    for (int mt = 0; mt < 2; mt++)
        #pragma unroll
        for (int nt = 0; nt < 4; nt++) {
            int r0 = base + wrow + mt * 16 + g2;
            int c  = nt * 8 + tc;
            if (r0 < n)
                *(float2*)(outp + (size_t)r0 * CH + c) = make_float2(df[mt][nt][0], df[mt][nt][1]);
            if (r0 + 8 < n)
                *(float2*)(outp + (size_t)(r0 + 8) * CH + c) = make_float2(df[mt][nt][2], df[mt][nt][3]);
        }

    // fused BN stats (deterministic)
    __syncthreads();
    float* ssum = (float*)smraw;                // 128*33
    float* ssq  = (float*)(smraw + 16896);
    #pragma unroll
    for (int mt = 0; mt < 2; mt++)
        #pragma unroll
        for (int nt = 0; nt < 4; nt++) {
            int rl = wrow + mt * 16 + g2;
            int c  = nt * 8 + tc;
            bool v0 = (base + rl) < n, v1 = (base + rl + 8) < n;
            float a = v0 ? df[mt][nt][0] : 0.f, b = v0 ? df[mt][nt][1] : 0.f;
            float cc = v1 ? df[mt][nt][2] : 0.f, dd = v1 ? df[mt][nt][3] : 0.f;
            ssum[rl * 33 + c] = a;        ssum[rl * 33 + c + 1] = b;
            ssum[(rl + 8) * 33 + c] = cc; ssum[(rl + 8) * 33 + c + 1] = dd;
            ssq[rl * 33 + c] = a * a;        ssq[rl * 33 + c + 1] = b * b;
            ssq[(rl + 8) * 33 + c] = cc * cc; ssq[(rl + 8) * 33 + c + 1] = dd * dd;
        }
    __syncthreads();
    if (t < 32) {
        float s = 0.f, q2 = 0.f;
        for (int i = 0; i < TM; i++) { s += ssum[i * 33 + t]; q2 += ssq[i * 33 + t]; }
        g_part[(size_t)blockIdx.x * 64 + t]      = s;
        g_part[(size_t)blockIdx.x * 64 + 32 + t] = q2;
    }
}

__global__ void ntrans(const int* __restrict__ nbr, int* __restrict__ nbrT, int n)
{
    int j = blockIdx.x * blockDim.x + threadIdx.x;
    int stride = gridDim.x * blockDim.x;
    for (int r = j; r < n; r += stride) {
        #pragma unroll
        for (int k = 0; k < KNB; k++)
            nbrT[(size_t)k * NPAD + r] = nbr[(size_t)r * KNB + k];
    }
}

// Pack W[k][ci][co] fp32 -> per-k B-fragment-ordered fp16 hi/lo image.
__global__ void wprep(const float* __restrict__ W, uint32_t* __restrict__ img)
{
    int i = blockIdx.x * blockDim.x + threadIdx.x;
    if (i >= KNB * 1024) return;
    int k = i >> 10, rem = i & 1023;
    int j = rem >> 7, lr = rem & 127, lane = lr >> 2, s = lr & 3;
    int f = 2 * j + (s >> 1), r = s & 1;
    int im = f >> 3, kt = (f >> 2) & 1, nt = f & 3;
    int ci0 = kt * 16 + r * 8 + (lane & 3) * 2;
    int co  = nt * 8 + (lane >> 2);
    float v0 = W[k * 1024 + ci0 * 32 + co];
    float v1 = W[k * 1024 + (ci0 + 1) * 32 + co];
    unsigned short p0, p1;
    if (im == 0) { p0 = f16u(v0); p1 = f16u(v1); }
    else {
        p0 = f16u(v0 - __half2float(__float2half_rn(v0)));
        p1 = f16u(v1 - __half2float(__float2half_rn(v1)));
    }
    img[i] = (uint32_t)p0 | ((uint32_t)p1 << 16);
}

// fp32 rows -> fp16 rows (64B)
__global__ void xprep(const float* __restrict__ x, uint32_t* __restrict__ xp, int n)
{
    int j = blockIdx.x * blockDim.x + threadIdx.x;
    int total = n * 8, stride = gridDim.x * blockDim.x;
    for (int i = j; i < total; i += stride) {
        int row = i >> 3, wp = i & 7;
        float4 v = *(const float4*)(x + (size_t)row * 32 + wp * 4);
        xp[(size_t)row * 16 + wp * 2]     = (uint32_t)f16u(v.x) | ((uint32_t)f16u(v.y) << 16);
        xp[(size_t)row * 16 + wp * 2 + 1] = (uint32_t)f16u(v.z) | ((uint32_t)f16u(v.w) << 16);
    }
}

// h1 fp32 -> BN+ReLU -> fp16 rows
__global__ void bnreluprep(const float* __restrict__ x, uint32_t* __restrict__ xp, int n)
{
    int j = blockIdx.x * blockDim.x + threadIdx.x;
    int total = n * 8, stride = gridDim.x * blockDim.x;
    int wp = j & 7;                          // stride multiple of 8 -> constant
    float4 sc = *(const float4*)(g_bn + wp * 4);
    float4 sh = *(const float4*)(g_bn + 32 + wp * 4);
    for (int i = j; i < total; i += stride) {
        int row = i >> 3;
        float4 v = *(const float4*)(x + (size_t)row * 32 + wp * 4);
        float a = fmaxf(v.x * sc.x + sh.x, 0.f);
        float b = fmaxf(v.y * sc.y + sh.y, 0.f);
        float c = fmaxf(v.z * sc.z + sh.z, 0.f);
        float d = fmaxf(v.w * sc.w + sh.w, 0.f);
        xp[(size_t)row * 16 + wp * 2]     = (uint32_t)f16u(a) | ((uint32_t)f16u(b) << 16);
        xp[(size_t)row * 16 + wp * 2 + 1] = (uint32_t)f16u(c) | ((uint32_t)f16u(d) << 16);
    }
}

__global__ void reduce_kernel(const float* __restrict__ gamma,
                              const float* __restrict__ beta, int n, int nblk)
{
    __shared__ double sd[512];
    __shared__ double comb[64];
    const int t = threadIdx.x;
    const int c = t & 63, s = t >> 6;
    double acc = 0.0;
    for (int i = s; i < nblk; i += 8) acc += (double)g_part[(size_t)i * 64 + c];
    sd[t] = acc;
    __syncthreads();
    if (t < 64) {
        double a = 0.0;
        #pragma unroll
        for (int s2 = 0; s2 < 8; s2++) a += sd[t + 64 * s2];
        comb[t] = a;
    }
    __syncthreads();
    if (t < 32) {
        double mean = comb[t] / (double)n;
        double var  = comb[32 + t] / (double)n - mean * mean;
        float sc = (float)((double)gamma[t] / sqrt(var + 1e-4));
        float sh = (float)((double)beta[t] - mean * (double)sc);
        g_bn[t] = sc; g_bn[32 + t] = sh;
    }
}

__global__ void final_kernel(float* __restrict__ out, const float* __restrict__ feat, int n)
{
    int j = blockIdx.x * blockDim.x + threadIdx.x;
    int total = n * 8, stride = gridDim.x * blockDim.x;
    int m = j & 7;
    float4 sc = *(const float4*)(g_bn + m * 4);
    float4 sh = *(const float4*)(g_bn + 32 + m * 4);
    float4* o4 = (float4*)out;
    const float4* f4 = (const float4*)feat;
    for (int i = j; i < total; i += stride) {
        float4 v = o4[i], f = f4[i];
        v.x = fmaxf(v.x * sc.x + sh.x + f.x, 0.f);
        v.y = fmaxf(v.y * sc.y + sh.y + f.y, 0.f);
        v.z = fmaxf(v.z * sc.z + sh.z + f.z, 0.f);
        v.w = fmaxf(v.w * sc.w + sh.w + f.w, 0.f);
        o4[i] = v;
    }
}

extern "C" void kernel_launch(void* const* d_in, const int* in_sizes, int n_in,
                              void* d_out, int out_size)
{
    const float* feat = (const float*)d_in[0];
    const int*   nbr  = (const int*)  d_in[1];
    const float* W1   = (const float*)d_in[2];
    const float* g1   = (const float*)d_in[3];
    const float* b1   = (const float*)d_in[4];
    const float* W2   = (const float*)d_in[5];
    const float* g2   = (const float*)d_in[6];
    const float* b2   = (const float*)d_in[7];
    int n = in_sizes[0] / CH;
    float* out = (float*)d_out;

    float* h1;
    uint32_t *xpf, *h1pf, *w1i, *w2i;
    int* nbrT;
    cudaGetSymbolAddress((void**)&h1,   g_h1);
    cudaGetSymbolAddress((void**)&xpf,  g_xp);
    cudaGetSymbolAddress((void**)&h1pf, g_h1p);
    cudaGetSymbolAddress((void**)&w1i,  g_w1img);
    cudaGetSymbolAddress((void**)&w2i,  g_w2img);
    cudaGetSymbolAddress((void**)&nbrT, g_nbrT);

    cudaFuncSetAttribute(conv_mma, cudaFuncAttributeMaxDynamicSharedMemorySize, SM_TOT);
    int grid = (n + TM - 1) / TM;

    ntrans<<<2048, 256>>>(nbr, nbrT, n);
    wprep<<<(KNB * 1024 + 255) / 256, 256>>>(W1, w1i);
    wprep<<<(KNB * 1024 + 255) / 256, 256>>>(W2, w2i);
    xprep<<<2048, 256>>>(feat, xpf, n);
    conv_mma<<<grid, 128, SM_TOT>>>(xpf, nbrT, w1i, h1, n);
    reduce_kernel<<<1, 512>>>(g1, b1, n, grid);
    bnreluprep<<<2048, 256>>>(h1, h1pf, n);
    conv_mma<<<grid, 128, SM_TOT>>>(h1pf, nbrT, w2i, out, n);
    reduce_kernel<<<1, 512>>>(g2, b2, n, grid);
    final_kernel<<<2048, 256>>>(out, feat, n);
}